// round 8
// baseline (speedup 1.0000x reference)
#include <cuda_runtime.h>
#include <cuda_bf16.h>

// Inputs (metadata order): data [E*3 f32], t0, tn, beta [1 f32], z0 [N*2 f32]
// Output: scalar f32 = -(sum(log_int) - sum(exp(log_int)))
//
// Math: li = beta - d,  d = |z_i - z_j|^2 in [0, 0.5)
//   sum(li)      = E*beta - sum(d)
//   sum(exp(li)) = exp(beta) * sum(exp(-d))
// exp(-d): degree-6 Taylor of e^u, u = 0.25 - d in [-0.25, 0.25], scaled by
// e^{-0.25}; max rel err ~1.2e-8. Pure FMA pipe.
//
// Tail: zero-atomic parity-flag rendezvous. Each block flips its flag with a
// release store after writing partials; block 0 acquire-polls all flags (one
// wave -> all blocks co-resident -> no deadlock), reduces, writes out.
// Flags flip once per launch => deterministic across graph replays.

#define MAX_BLOCKS 512

__device__ float g_block[2 * MAX_BLOCKS];      // per-block partials (plain STG)
__device__ unsigned int g_flag[MAX_BLOCKS];    // parity flags (release/acquire)

#define C0 0.7788007830714049f
#define C1 0.7788007830714049f
#define C2 0.38940039153570246f
#define C3 0.12980013051190082f
#define C4 0.032450032627975205f
#define C5 0.006490006525595041f
#define C6 0.0010816677542658402f

__device__ __forceinline__ float exp_negd(float d) {
    float u = 0.25f - d;
    float p = C6;
    p = fmaf(p, u, C5);
    p = fmaf(p, u, C4);
    p = fmaf(p, u, C3);
    p = fmaf(p, u, C2);
    p = fmaf(p, u, C1);
    p = fmaf(p, u, C0);
    return p;
}

__device__ __forceinline__ void do_quad(const float2* __restrict__ tab,
                                        float4 a, float4 b, float4 c,
                                        float& s_d, float& s_e)
{
    int i0 = __float2int_rz(a.x), j0 = __float2int_rz(a.y);
    int i1 = __float2int_rz(a.w), j1 = __float2int_rz(b.x);
    int i2 = __float2int_rz(b.z), j2 = __float2int_rz(b.w);
    int i3 = __float2int_rz(c.y), j3 = __float2int_rz(c.z);

    float2 zi0 = tab[i0], zj0 = tab[j0];
    float2 zi1 = tab[i1], zj1 = tab[j1];
    float2 zi2 = tab[i2], zj2 = tab[j2];
    float2 zi3 = tab[i3], zj3 = tab[j3];

    float dx0 = zi0.x - zj0.x, dy0 = zi0.y - zj0.y;
    float dx1 = zi1.x - zj1.x, dy1 = zi1.y - zj1.y;
    float dx2 = zi2.x - zj2.x, dy2 = zi2.y - zj2.y;
    float dx3 = zi3.x - zj3.x, dy3 = zi3.y - zj3.y;

    float d0 = fmaf(dx0, dx0, dy0 * dy0);
    float d1 = fmaf(dx1, dx1, dy1 * dy1);
    float d2 = fmaf(dx2, dx2, dy2 * dy2);
    float d3 = fmaf(dx3, dx3, dy3 * dy3);

    s_d += (d0 + d1) + (d2 + d3);
    s_e += (exp_negd(d0) + exp_negd(d1)) + (exp_negd(d2) + exp_negd(d3));
}

__device__ __forceinline__ unsigned ld_acquire_u32(const unsigned int* p) {
    unsigned v;
    asm volatile("ld.global.acquire.gpu.u32 %0, [%1];"
                 : "=r"(v) : "l"(p) : "memory");
    return v;
}

__device__ __forceinline__ void st_release_u32(unsigned int* p, unsigned v) {
    asm volatile("st.global.release.gpu.u32 [%0], %1;"
                 :: "l"(p), "r"(v) : "memory");
}

__global__ void __launch_bounds__(1024, 1)
nll_kernel(const float* __restrict__ data,
           const float* __restrict__ beta,
           const float* __restrict__ z0,
           float* __restrict__ out,
           int E, int N)
{
    extern __shared__ float2 tab[];   // N float2 = 80 KB for N=10000

    const int T = gridDim.x * blockDim.x;
    const int gtid = blockIdx.x * blockDim.x + threadIdx.x;
    const int nquad = E >> 2;
    const float4* dp = (const float4*)data;

    // ---- 1) stage z0 into shared memory (cp.async fill) ----
    {
        int nv = (N * 2) >> 2;               // float4 count (5000 for N=10000)
        const float4* z4 = (const float4*)z0;
        for (int k = threadIdx.x; k < nv; k += blockDim.x) {
            unsigned int dst = (unsigned int)__cvta_generic_to_shared(
                                   (float4*)tab + k);
            asm volatile("cp.async.cg.shared.global [%0], [%1], 16;\n"
                         :: "r"(dst), "l"(z4 + k));
        }
        asm volatile("cp.async.commit_group;\n" ::: "memory");
        int rem_base = nv << 2;              // scalar remainder (rare)
        for (int k = rem_base + threadIdx.x; k < N * 2; k += blockDim.x)
            ((float*)tab)[k] = z0[k];
        asm volatile("cp.async.wait_group 0;\n" ::: "memory");
    }
    __syncthreads();

    float s_d = 0.0f;
    float s_e = 0.0f;

    // ---- 2) batch both quads' LDGs after the sync ----
    {
        const int q0 = gtid;
        const int q1 = gtid + T;
        const bool h0 = (q0 < nquad);
        const bool h1 = (q1 < nquad);
        float4 a0, b0, c0, a1, b1, c1;
        if (h0) {
            a0 = dp[3 * q0 + 0];
            b0 = dp[3 * q0 + 1];
            c0 = dp[3 * q0 + 2];
        }
        if (h1) {
            a1 = dp[3 * q1 + 0];
            b1 = dp[3 * q1 + 1];
            c1 = dp[3 * q1 + 2];
        }
        if (h0) do_quad(tab, a0, b0, c0, s_d, s_e);
        if (h1) do_quad(tab, a1, b1, c1, s_d, s_e);
    }

    // ---- 2b) generic overflow (not taken for E=1M @ grid 148×1024) ----
    for (int q = gtid + 2 * T; q < nquad; q += T) {
        float4 aa = dp[3 * q + 0];
        float4 bb = dp[3 * q + 1];
        float4 cc = dp[3 * q + 2];
        do_quad(tab, aa, bb, cc, s_d, s_e);
    }

    // ---- 2c) tail events (E % 4) ----
    {
        int rbase = nquad << 2;
        int r = E - rbase;
        if (gtid < r) {
            int e = rbase + gtid;
            int i = __float2int_rz(data[3 * e + 0]);
            int j = __float2int_rz(data[3 * e + 1]);
            float2 zi = tab[i], zj = tab[j];
            float dx = zi.x - zj.x, dy = zi.y - zj.y;
            float d = fmaf(dx, dx, dy * dy);
            s_d += d;
            s_e += exp_negd(d);
        }
    }

    // ---- warp reduction ----
    #pragma unroll
    for (int o = 16; o > 0; o >>= 1) {
        s_d += __shfl_xor_sync(0xffffffffu, s_d, o);
        s_e += __shfl_xor_sync(0xffffffffu, s_e, o);
    }

    // ---- block reduction ----
    __shared__ float sm_d[32];
    __shared__ float sm_e[32];
    const int lane = threadIdx.x & 31;
    const int warp = threadIdx.x >> 5;
    if (lane == 0) { sm_d[warp] = s_d; sm_e[warp] = s_e; }
    __syncthreads();

    if (warp == 0) {
        const int nwarps = blockDim.x >> 5;
        s_d = (lane < nwarps) ? sm_d[lane] : 0.0f;
        s_e = (lane < nwarps) ? sm_e[lane] : 0.0f;
        #pragma unroll
        for (int o = 16; o > 0; o >>= 1) {
            s_d += __shfl_xor_sync(0xffffffffu, s_d, o);
            s_e += __shfl_xor_sync(0xffffffffu, s_e, o);
        }

        // ---- zero-atomic parity-flag rendezvous ----
        unsigned newf = 0;
        if (lane == 0) {
            g_block[2 * blockIdx.x + 0] = s_d;
            g_block[2 * blockIdx.x + 1] = s_e;
            unsigned oldf = __ldcg(&g_flag[blockIdx.x]);
            newf = oldf ^ 1u;
            // release store: orders the partial STGs before the flag flip
            st_release_u32(&g_flag[blockIdx.x], newf);
        }

        if (blockIdx.x == 0) {
            // block 0 waits for every block's flag to reach this launch's
            // parity, then reduces. All blocks are co-resident (one wave),
            // so polling cannot deadlock.
            const unsigned expect = __shfl_sync(0xffffffffu, newf, 0);
            bool done = false;
            while (!done) {
                bool mine = true;
                for (int b = lane; b < (int)gridDim.x; b += 32)
                    mine &= (ld_acquire_u32(&g_flag[b]) == expect);
                done = __all_sync(0xffffffffu, mine);
            }

            float fd = 0.0f, fe = 0.0f;
            for (int b = lane; b < (int)gridDim.x; b += 32) {
                fd += __ldcg(&g_block[2 * b + 0]);
                fe += __ldcg(&g_block[2 * b + 1]);
            }
            #pragma unroll
            for (int o = 16; o > 0; o >>= 1) {
                fd += __shfl_xor_sync(0xffffffffu, fd, o);
                fe += __shfl_xor_sync(0xffffffffu, fe, o);
            }
            if (lane == 0) {
                float bb = beta[0];
                float sl = (float)E * bb - fd;     // sum(log intensities)
                float se = expf(bb) * fe;          // sum(exp(log intensities))
                out[0] = se - sl;                  // -(sl - se)
            }
        }
    }
}

extern "C" void kernel_launch(void* const* d_in, const int* in_sizes, int n_in,
                              void* d_out, int out_size)
{
    const float* data = (const float*)d_in[0];
    // d_in[1] = t0, d_in[2] = tn  (unused)
    const float* beta = (const float*)d_in[3];
    const float* z0   = (const float*)d_in[4];
    float* out = (float*)d_out;

    const int E = in_sizes[0] / 3;
    const int N = in_sizes[4] / 2;
    const size_t smem = (size_t)N * sizeof(float2);   // 80 KB for N=10000

    cudaFuncSetAttribute(nll_kernel,
                         cudaFuncAttributeMaxDynamicSharedMemorySize,
                         (int)smem);

    const int threads = 1024;
    int blocks = 148;                                  // 1 block/SM, one wave
    int max_blocks = (E + threads - 1) / threads;
    if (blocks > max_blocks) blocks = max_blocks;
    if (blocks > MAX_BLOCKS) blocks = MAX_BLOCKS;

    nll_kernel<<<blocks, threads, smem>>>(data, beta, z0, out, E, N);
}

// round 9
// speedup vs baseline: 1.2179x; 1.2179x over previous
#include <cuda_runtime.h>
#include <cuda_bf16.h>

// Inputs (metadata order): data [E*3 f32], t0, tn, beta [1 f32], z0 [N*2 f32]
// Output: scalar f32 = -(sum(log_int) - sum(exp(log_int)))
//
// Math: li = beta - d,  d = |z_i - z_j|^2 in [0, 0.5)
//   sum(li)      = E*beta - sum(d)
//   sum(exp(li)) = exp(beta) * sum(exp(-d))
// exp(-d) = 2^(-d*log2e) via single MUFU ex2.approx (rel err ~2^-22).
//
// Structure: R2 (measured champion, 9.57us kernel) with ONLY the exp changed
// from 7-FMA Taylor to MUFU ex2.

__device__ float g_partial[2];        // [0]=sum(d), [1]=sum(exp(-d)); zero-init
__device__ unsigned int g_ticket;     // wraps via atomicInc -> replay-safe

__device__ __forceinline__ float exp_negd(float d) {
    // exp(-d) = exp2(-d * log2(e)); single MUFU.EX2
    float x = d * -1.4426950408889634f;
    float r;
    asm("ex2.approx.ftz.f32 %0, %1;" : "=f"(r) : "f"(x));
    return r;
}

__global__ void __launch_bounds__(1024, 1)
nll_kernel(const float* __restrict__ data,
           const float* __restrict__ beta,
           const float* __restrict__ z0,
           float* __restrict__ out,
           int E, int N)
{
    extern __shared__ float2 tab[];   // N float2 = 80 KB for N=10000

    // ---- stage z0 table into shared memory (coalesced float4, as R2) ----
    {
        const float4* z4 = (const float4*)z0;
        float4* t4 = (float4*)tab;
        int nv = (N * 2) >> 2;                 // float4 count
        for (int k = threadIdx.x; k < nv; k += blockDim.x)
            t4[k] = z4[k];
        int rem_base = nv << 2;                // scalar remainder
        for (int k = rem_base + threadIdx.x; k < N * 2; k += blockDim.x)
            ((float*)tab)[k] = z0[k];
    }
    __syncthreads();

    float s_d = 0.0f;   // sum of d
    float s_e = 0.0f;   // sum of exp(-d)

    const int T = gridDim.x * blockDim.x;
    const int gtid = blockIdx.x * blockDim.x + threadIdx.x;
    const int nquad = E >> 2;
    const float4* dp = (const float4*)data;   // 3 float4 per 4 events

    for (int q = gtid; q < nquad; q += T) {
        float4 a = dp[3 * q + 0];   // i0 j0 t0 i1
        float4 b = dp[3 * q + 1];   // j1 t1 i2 j2
        float4 c = dp[3 * q + 2];   // t2 i3 j3 t3

        int i0 = __float2int_rz(a.x), j0 = __float2int_rz(a.y);
        int i1 = __float2int_rz(a.w), j1 = __float2int_rz(b.x);
        int i2 = __float2int_rz(b.z), j2 = __float2int_rz(b.w);
        int i3 = __float2int_rz(c.y), j3 = __float2int_rz(c.z);

        float2 zi0 = tab[i0], zj0 = tab[j0];
        float2 zi1 = tab[i1], zj1 = tab[j1];
        float2 zi2 = tab[i2], zj2 = tab[j2];
        float2 zi3 = tab[i3], zj3 = tab[j3];

        float dx0 = zi0.x - zj0.x, dy0 = zi0.y - zj0.y;
        float dx1 = zi1.x - zj1.x, dy1 = zi1.y - zj1.y;
        float dx2 = zi2.x - zj2.x, dy2 = zi2.y - zj2.y;
        float dx3 = zi3.x - zj3.x, dy3 = zi3.y - zj3.y;

        float d0 = fmaf(dx0, dx0, dy0 * dy0);
        float d1 = fmaf(dx1, dx1, dy1 * dy1);
        float d2 = fmaf(dx2, dx2, dy2 * dy2);
        float d3 = fmaf(dx3, dx3, dy3 * dy3);

        s_d += (d0 + d1) + (d2 + d3);
        s_e += (exp_negd(d0) + exp_negd(d1)) + (exp_negd(d2) + exp_negd(d3));
    }

    // tail events (E % 4)
    {
        int rbase = nquad << 2;
        int r = E - rbase;
        if (gtid < r) {
            int e = rbase + gtid;
            int i = __float2int_rz(data[3 * e + 0]);
            int j = __float2int_rz(data[3 * e + 1]);
            float2 zi = tab[i], zj = tab[j];
            float dx = zi.x - zj.x, dy = zi.y - zj.y;
            float d = fmaf(dx, dx, dy * dy);
            s_d += d;
            s_e += exp_negd(d);
        }
    }

    // ---- warp reduction ----
    #pragma unroll
    for (int o = 16; o > 0; o >>= 1) {
        s_d += __shfl_xor_sync(0xffffffffu, s_d, o);
        s_e += __shfl_xor_sync(0xffffffffu, s_e, o);
    }

    // ---- block reduction ----
    __shared__ float sm_d[32];
    __shared__ float sm_e[32];
    const int lane = threadIdx.x & 31;
    const int warp = threadIdx.x >> 5;
    if (lane == 0) { sm_d[warp] = s_d; sm_e[warp] = s_e; }
    __syncthreads();

    if (warp == 0) {
        const int nwarps = blockDim.x >> 5;
        s_d = (lane < nwarps) ? sm_d[lane] : 0.0f;
        s_e = (lane < nwarps) ? sm_e[lane] : 0.0f;
        #pragma unroll
        for (int o = 16; o > 0; o >>= 1) {
            s_d += __shfl_xor_sync(0xffffffffu, s_d, o);
            s_e += __shfl_xor_sync(0xffffffffu, s_e, o);
        }
        if (lane == 0) {
            atomicAdd(&g_partial[0], s_d);
            atomicAdd(&g_partial[1], s_e);
            __threadfence();
            unsigned t = atomicInc(&g_ticket, gridDim.x - 1);  // wraps
            if (t == gridDim.x - 1) {
                // read + reset scratch (deterministic across graph replays)
                float Sd = atomicExch(&g_partial[0], 0.0f);
                float Se = atomicExch(&g_partial[1], 0.0f);
                float b = beta[0];
                float sl = (float)E * b - Sd;       // sum(log intensities)
                float se = expf(b) * Se;            // sum(exp(log intensities))
                out[0] = se - sl;                   // -(sl - se)
            }
        }
    }
}

extern "C" void kernel_launch(void* const* d_in, const int* in_sizes, int n_in,
                              void* d_out, int out_size)
{
    const float* data = (const float*)d_in[0];
    // d_in[1] = t0, d_in[2] = tn  (unused)
    const float* beta = (const float*)d_in[3];
    const float* z0   = (const float*)d_in[4];
    float* out = (float*)d_out;

    const int E = in_sizes[0] / 3;
    const int N = in_sizes[4] / 2;
    const size_t smem = (size_t)N * sizeof(float2);   // 80 KB for N=10000

    cudaFuncSetAttribute(nll_kernel,
                         cudaFuncAttributeMaxDynamicSharedMemorySize,
                         (int)smem);

    const int threads = 1024;
    int blocks = 148;                                  // 1 block/SM, one wave
    int max_blocks = (E + threads - 1) / threads;
    if (blocks > max_blocks) blocks = max_blocks;

    nll_kernel<<<blocks, threads, smem>>>(data, beta, z0, out, E, N);
}